// round 7
// baseline (speedup 1.0000x reference)
#include <cuda_runtime.h>
#include <math.h>

#define B_   4
#define S_   2048
#define DIN  512
#define U_   64
#define L_OUT 132064

typedef unsigned long long ull;

// ---------------- f32x2 packed helpers (sm_103a) ----------------
__device__ __forceinline__ ull dup2(float x) {
    ull r; asm("mov.b64 %0, {%1, %1};" : "=l"(r) : "f"(x)); return r;
}
__device__ __forceinline__ void fma2(ull &d, ull a, ull b) {
    asm("fma.rn.f32x2 %0, %1, %2, %3;" : "=l"(d) : "l"(a), "l"(b), "l"(d));
}
__device__ __forceinline__ ull mul2(ull a, ull b) {
    ull d; asm("mul.rn.f32x2 %0, %1, %2;" : "=l"(d) : "l"(a), "l"(b)); return d;
}
__device__ __forceinline__ float2 unpk(ull v) {
    float2 f; asm("mov.b64 {%0, %1}, %2;" : "=f"(f.x), "=f"(f.y) : "l"(v)); return f;
}

// ---------------- scratch ----------------
__device__ float g_Q[B_ * S_ * U_];
__device__ float g_K[B_ * S_ * U_];
__device__ float g_V[B_ * S_ * U_];

// ======================= Kernel A: QKV projections =======================
// Tile M=64 x N=64, 128 threads. Per-thread 4m x 8n (n-pairs packed -> no B dup).
// K-chunk 64, register prefetch of next chunk's gmem loads.
__global__ __launch_bounds__(128, 3)
void proj_kernel(const float* __restrict__ query,
                 const float* __restrict__ value,
                 const float* __restrict__ Wq, const float* __restrict__ bq,
                 const float* __restrict__ Wk, const float* __restrict__ bk,
                 const float* __restrict__ Wv, const float* __restrict__ bv)
{
    const int p = blockIdx.y;
    const float* X  = (p == 0) ? query : value;
    const float* Wm = (p == 0) ? Wq : ((p == 1) ? Wk : Wv);
    const float* bm = (p == 0) ? bq : ((p == 1) ? bk : bv);
    float* O        = (p == 0) ? g_Q : ((p == 1) ? g_K : g_V);

    const int m0 = blockIdx.x * 64;
    const int tid = threadIdx.x;

    __shared__ float Ast[64][68];   // [k][m]
    __shared__ float Bs [64][68];   // [k][n]

    // compute roles
    const int tx  = tid & 7;        // n-group: 8 n (4 pairs)
    const int tym = tid >> 3;       // m-group: 4 m (0..15)

    // loader roles
    const int lmA = tid >> 1;             // A row 0..63
    const int lkA = (tid & 1) * 32;       // A k-half
    const int lkB = tid >> 1;             // B k-row 0..63
    const int lnB = (tid & 1) * 4;        // B n interleave base

    ull acc2[4][4];
    #pragma unroll
    for (int i = 0; i < 4; ++i)
        #pragma unroll
        for (int j = 0; j < 4; ++j) acc2[i][j] = 0ull;

    float4 aR[8], bR[8];

    // prefetch chunk 0
    #pragma unroll
    for (int it = 0; it < 8; ++it) {
        aR[it] = *(const float4*)&X[(size_t)(m0 + lmA) * DIN + lkA + it * 4];
        bR[it] = *(const float4*)&Wm[(size_t)lkB * U_ + lnB + it * 8];
    }

    for (int k0 = 0; k0 < DIN; k0 += 64) {
        // store staged regs to smem
        #pragma unroll
        for (int it = 0; it < 8; ++it) {
            const int ka = lkA + it * 4;
            Ast[ka + 0][lmA] = aR[it].x;
            Ast[ka + 1][lmA] = aR[it].y;
            Ast[ka + 2][lmA] = aR[it].z;
            Ast[ka + 3][lmA] = aR[it].w;
            *(float4*)&Bs[lkB][lnB + it * 8] = bR[it];
        }
        __syncthreads();

        // prefetch next chunk
        if (k0 + 64 < DIN) {
            #pragma unroll
            for (int it = 0; it < 8; ++it) {
                aR[it] = *(const float4*)&X[(size_t)(m0 + lmA) * DIN + k0 + 64 + lkA + it * 4];
                bR[it] = *(const float4*)&Wm[(size_t)(k0 + 64 + lkB) * U_ + lnB + it * 8];
            }
        }

        #pragma unroll 4
        for (int k = 0; k < 64; ++k) {
            float4 af = *(const float4*)&Ast[k][tym * 4];
            ulonglong2 b01 = *(const ulonglong2*)&Bs[k][tx * 8];
            ulonglong2 b23 = *(const ulonglong2*)&Bs[k][tx * 8 + 4];
            ull a0 = dup2(af.x), a1 = dup2(af.y), a2 = dup2(af.z), a3 = dup2(af.w);
            fma2(acc2[0][0], a0, b01.x); fma2(acc2[0][1], a0, b01.y);
            fma2(acc2[0][2], a0, b23.x); fma2(acc2[0][3], a0, b23.y);
            fma2(acc2[1][0], a1, b01.x); fma2(acc2[1][1], a1, b01.y);
            fma2(acc2[1][2], a1, b23.x); fma2(acc2[1][3], a1, b23.y);
            fma2(acc2[2][0], a2, b01.x); fma2(acc2[2][1], a2, b01.y);
            fma2(acc2[2][2], a2, b23.x); fma2(acc2[2][3], a2, b23.y);
            fma2(acc2[3][0], a3, b01.x); fma2(acc2[3][1], a3, b01.y);
            fma2(acc2[3][2], a3, b23.x); fma2(acc2[3][3], a3, b23.y);
        }
        __syncthreads();
    }

    // epilogue: bias + store (n-pairs are contiguous)
    float4 bias01 = *(const float4*)&bm[tx * 8];
    float4 bias23 = *(const float4*)&bm[tx * 8 + 4];
    #pragma unroll
    for (int mi = 0; mi < 4; ++mi) {
        float2 p0 = unpk(acc2[mi][0]);
        float2 p1 = unpk(acc2[mi][1]);
        float2 p2 = unpk(acc2[mi][2]);
        float2 p3 = unpk(acc2[mi][3]);
        float4 o0 = {p0.x + bias01.x, p0.y + bias01.y, p1.x + bias01.z, p1.y + bias01.w};
        float4 o1 = {p2.x + bias23.x, p2.y + bias23.y, p3.x + bias23.z, p3.y + bias23.w};
        const size_t row = (size_t)(m0 + tym * 4 + mi) * U_;
        *(float4*)&O[row + tx * 8]     = o0;
        *(float4*)&O[row + tx * 8 + 4] = o1;
    }
}

// ======================= Kernel B: banded attention =======================
// TJ=32 j per block, 16 warps, 2 j per warp (half-warp = one j, float4/lane).
#define TJ   32
#define NBK  160            // K band rows
#define NBV  162            // V band rows (+2 zero pad)
#define KP   68             // K row stride (floats)

__device__ __forceinline__ int off_of(int s)
{
    if (s <= 32)   return s * 33 + (s * (s - 1)) / 2;
    if (s <= 2016) return 1552 + (s - 32) * 65;
    return 130512 + ((2145 - s) * (s - 2016)) / 2;
}

extern __shared__ float sm_b[];

__global__ __launch_bounds__(512, 2)
void attn_kernel(float* __restrict__ out)
{
    float* Ks = sm_b;                 // [NBK][KP]
    float* Vs = Ks + NBK * KP;        // [NBV][64]
    float* Qs = Vs + NBV * 64;        // [TJ][64]
    float* Es = Qs + TJ * 64;         // [TJ][132]

    const int b     = blockIdx.y;
    const int j0    = blockIdx.x * TJ;
    const int tid   = threadIdx.x;    // 512
    const int ubase = j0 - 64;

    // ---- tile loads + zero padding ----
    {
        const size_t gbase = (size_t)b * S_ * U_;
        for (int i = tid; i < TJ * 16; i += 512)
            *(float4*)&Qs[i * 4] = *(const float4*)&g_Q[gbase + (size_t)j0 * U_ + i * 4];
        for (int i = tid; i < NBK * 16; i += 512) {
            const int ug = i >> 4, d4 = (i & 15) << 2;
            int u = ubase + ug;
            u = (u < 0) ? 0 : ((u > S_ - 1) ? S_ - 1 : u);
            *(float4*)&Ks[ug * KP + d4] = *(const float4*)&g_K[gbase + (size_t)u * U_ + d4];
            *(float4*)&Vs[ug * 64 + d4] = *(const float4*)&g_V[gbase + (size_t)u * U_ + d4];
        }
        // zero V pad rows 160,161
        for (int i = tid; i < 2 * 16; i += 512) {
            const int ug = 160 + (i >> 4), d4 = (i & 15) << 2;
            *(float4*)&Vs[ug * 64 + d4] = make_float4(0.f, 0.f, 0.f, 0.f);
        }
        // zero Es (cols 129..131 must be 0; rest overwritten by phase 1)
        for (int i = tid; i < TJ * 132 / 4; i += 512)
            *(float4*)&Es[i * 4] = make_float4(0.f, 0.f, 0.f, 0.f);
    }
    __syncthreads();

    const int w    = tid >> 5;        // warp 0..15
    const int lane = tid & 31;
    const int jg   = lane >> 4;       // 0/1: which j of the pair
    const int ul   = lane & 15;
    const int j_a  = j0 + 2 * w;
    const int jme  = j_a + jg;

    // ---- phase 1: band scores, 2 j per warp sharing K rows ----
    {
        float acc[9];
        int rowoff[9];
        #pragma unroll
        for (int t = 0; t < 9; ++t) {
            acc[t] = 0.f;
            int r = ul + 16 * t; if (r > 129) r = 129;
            rowoff[t] = (2 * w + r) * KP;
        }
        const float* qp = Qs + (2 * w + jg) * 64;
        #pragma unroll 4
        for (int d4 = 0; d4 < 64; d4 += 4) {
            float4 q = *(const float4*)&qp[d4];
            #pragma unroll
            for (int t = 0; t < 9; ++t) {
                float4 kf = *(const float4*)&Ks[rowoff[t] + d4];
                acc[t] += q.x * kf.x + q.y * kf.y + q.z * kf.z + q.w * kf.w;
            }
        }
        const float NEG_INF = __int_as_float(0xff800000);
        float sc[9], m = NEG_INF;
        #pragma unroll
        for (int t = 0; t < 9; ++t) {
            const int r  = ul + 16 * t;
            const int uu = r - jg;
            const int u  = ubase + 2 * w + r;
            const bool valid = (uu >= 0) && (uu <= 128) && (u >= 0) && (u < S_);
            sc[t] = valid ? acc[t] * 0.125f : NEG_INF;
            m = fmaxf(m, sc[t]);
        }
        #pragma unroll
        for (int off = 8; off > 0; off >>= 1)         // reduce within 16-lane half
            m = fmaxf(m, __shfl_xor_sync(0xffffffffu, m, off));
        float* erow = Es + (2 * w + jg) * 132;
        #pragma unroll
        for (int t = 0; t < 9; ++t) {
            const int uu = ul + 16 * t - jg;
            if (uu >= 0 && uu <= 128)
                erow[uu] = __expf(sc[t] - m);
        }
    }
    __syncthreads();

    // ---- phase 2: unified predicated sliding-window loop ----
    {
        const int dl = lane & 15;                 // float4 index along d
        const int smin_u = (j_a - 32 > 0) ? (j_a - 32) : 0;          // union start
        const int smax_u = (j_a + 33 < S_ - 1) ? (j_a + 33) : (S_ - 1); // union end (= smax of j_b)
        const int slo = (jme - 32 > 0) ? (jme - 32) : 0;  // my store range
        const int shi = (jme + 32 < S_ - 1) ? (jme + 32) : (S_ - 1);

        const float* ej = Es + (2 * w + jg) * 132 + 64 - jme; // index by absolute u
        // init window at s = smin_u: u in [max(smin_u-32,0), min(smin_u+33,S_))
        float Dv = 0.f; ull n0 = 0ull, n1 = 0ull;
        {
            const int ulo = (smin_u - 32 > 0) ? (smin_u - 32) : 0;
            const int uhi = (smin_u + 33 < S_) ? (smin_u + 33) : S_;
            const float* pe = ej + ulo;
            const float* pv = Vs + (ulo - ubase) * 64 + dl * 4;
            for (int u = ulo; u < uhi; ++u) {
                const float e = *pe++;
                const ulonglong2 v = *(const ulonglong2*)pv; pv += 64;
                const ull ed = dup2(e);
                fma2(n0, ed, v.x); fma2(n1, ed, v.y);
                Dv += e;
            }
        }

        const int start0 = (smin_u - 32 > 0) ? (smin_u - 32) : 0;
        float* po = out + (size_t)b * L_OUT * U_
                        + ((size_t)off_of(smin_u) + (jme - start0)) * U_ + dl * 4;
        const float* pea = ej + smin_u + 33;
        const float* pes = ej + smin_u - 32;
        const float* pva = Vs + (smin_u + 33 - ubase) * 64 + dl * 4;
        const float* pvs = Vs + (smin_u - 32 - ubase) * 64 + dl * 4;

        for (int s = smin_u; s <= smax_u; ++s) {
            if (s >= slo && s <= shi) {
                const float invD = __fdividef(1.f, Dv);
                const ull dd = dup2(invD);
                ulonglong2 o; o.x = mul2(n0, dd); o.y = mul2(n1, dd);
                *(ulonglong2*)po = o;
            }
            int delta = s + 33; if (delta > 64) delta = 64;
            int d2 = 2079 - s;  if (d2 < delta) delta = d2;
            po += (size_t)delta * U_;

            const float ea = *pea++;
            const float es = *pes++;
            const ulonglong2 va = *(const ulonglong2*)pva; pva += 64;
            const ulonglong2 vv = *(const ulonglong2*)pvs; pvs += 64;
            const ull ead = dup2(ea);
            fma2(n0, ead, va.x); fma2(n1, ead, va.y);
            const ull esd = dup2(-es);
            fma2(n0, esd, vv.x); fma2(n1, esd, vv.y);
            Dv += (ea - es);
        }
    }
}

// ======================= launch =======================
extern "C" void kernel_launch(void* const* d_in, const int* in_sizes, int n_in,
                              void* d_out, int out_size)
{
    const float* query = (const float*)d_in[0];
    const float* value = (const float*)d_in[1];
    const float* Wq    = (const float*)d_in[2];
    const float* bq    = (const float*)d_in[3];
    const float* Wk    = (const float*)d_in[4];
    const float* bk    = (const float*)d_in[5];
    const float* Wv    = (const float*)d_in[6];
    const float* bv    = (const float*)d_in[7];
    float* out = (float*)d_out;

    dim3 gA((B_ * S_) / 64, 3);
    proj_kernel<<<gA, 128>>>(query, value, Wq, bq, Wk, bk, Wv, bv);

    const int smem_bytes = (NBK * KP + NBV * 64 + TJ * 64 + TJ * 132) * (int)sizeof(float);
    cudaFuncSetAttribute(attn_kernel, cudaFuncAttributeMaxDynamicSharedMemorySize, smem_bytes);
    dim3 gB(S_ / TJ, B_);
    attn_kernel<<<gB, 512, smem_bytes>>>(out);
}

// round 10
// speedup vs baseline: 1.2067x; 1.2067x over previous
#include <cuda_runtime.h>
#include <math.h>
#include <stdint.h>

#define B_   4
#define S_   2048
#define DIN  512
#define U_   64
#define L_OUT 132064

typedef unsigned long long ull;

// ---------------- f32x2 packed helpers (sm_103a) ----------------
__device__ __forceinline__ ull dup2(float x) {
    ull r; asm("mov.b64 %0, {%1, %1};" : "=l"(r) : "f"(x)); return r;
}
__device__ __forceinline__ void fma2(ull &d, ull a, ull b) {
    asm("fma.rn.f32x2 %0, %1, %2, %3;" : "=l"(d) : "l"(a), "l"(b), "l"(d));
}
__device__ __forceinline__ ull mul2(ull a, ull b) {
    ull d; asm("mul.rn.f32x2 %0, %1, %2;" : "=l"(d) : "l"(a), "l"(b)); return d;
}
__device__ __forceinline__ float2 unpk(ull v) {
    float2 f; asm("mov.b64 {%0, %1}, %2;" : "=f"(f.x), "=f"(f.y) : "l"(v)); return f;
}

// ---------------- cp.async helpers ----------------
__device__ __forceinline__ uint32_t smem_u32(const void* p) {
    uint32_t a;
    asm("{ .reg .u64 t; cvta.to.shared.u64 t, %1; cvt.u32.u64 %0, t; }" : "=r"(a) : "l"(p));
    return a;
}
__device__ __forceinline__ void cp4(uint32_t dst, const void* src) {
    asm volatile("cp.async.ca.shared.global [%0], [%1], 4;" :: "r"(dst), "l"(src));
}
__device__ __forceinline__ void cp16(uint32_t dst, const void* src) {
    asm volatile("cp.async.cg.shared.global [%0], [%1], 16;" :: "r"(dst), "l"(src));
}
__device__ __forceinline__ void cp_commit() {
    asm volatile("cp.async.commit_group;" ::: "memory");
}
__device__ __forceinline__ void cp_wait0() {
    asm volatile("cp.async.wait_group 0;" ::: "memory");
}

// ---------------- scratch ----------------
__device__ float g_Q[B_ * S_ * U_];
__device__ float g_K[B_ * S_ * U_];
__device__ float g_V[B_ * S_ * U_];

// ======================= Kernel A: QKV projections (f32x2, 8x8 tiles) =======================
// Tile M=128 x N=64, 128 threads, per-thread 8m x 8n. K chunks of 64, cp.async double-buffer.
// smem stage: A[128][69] fp32 (8832 fl) + B[64][68] (4352 fl) = 13184 fl = 52736 B; x2 stages.
#define AP  69
#define BP  68
#define STG_FL 13184
#define PROJ_SMEM (2 * STG_FL * 4)

extern __shared__ float prsm[];

__global__ __launch_bounds__(128, 2)
void proj_kernel(const float* __restrict__ query,
                 const float* __restrict__ value,
                 const float* __restrict__ Wq, const float* __restrict__ bq,
                 const float* __restrict__ Wk, const float* __restrict__ bk,
                 const float* __restrict__ Wv, const float* __restrict__ bv)
{
    const int p = blockIdx.y;
    const float* X  = (p == 0) ? query : value;
    const float* Wm = (p == 0) ? Wq : ((p == 1) ? Wk : Wv);
    const float* bm = (p == 0) ? bq : ((p == 1) ? bk : bv);
    float* O        = (p == 0) ? g_Q : ((p == 1) ? g_K : g_V);

    const int m0  = blockIdx.x * 128;
    const int tid = threadIdx.x;

    const uint32_t sbase = smem_u32(prsm);

    // compute roles: 16 m-groups (8 rows) x 8 n-groups (8 cols)
    const int tx  = tid & 7;         // n: cols tx*8 .. tx*8+7
    const int tym = tid >> 3;        // m: rows tym*8 .. tym*8+7

    // loader roles
    const int lmA = tid >> 2;                 // not used directly; see loops

    ull acc[8][4];
    #pragma unroll
    for (int i = 0; i < 8; ++i)
        #pragma unroll
        for (int j = 0; j < 4; ++j) acc[i][j] = 0ull;

    // ---- stage loader (cp.async) ----
    auto stage_load = [&](int buf, int c) {
        const int k0 = c * 64;
        const uint32_t sA = sbase + (uint32_t)(buf * STG_FL) * 4;
        const uint32_t sB = sA + 8832u * 4;
        // A: 128 rows x 64 k, scalar 4B cp.async, coalesced (warp = 32 consecutive k of one row)
        #pragma unroll
        for (int it = 0; it < 64; ++it) {
            const int i = tid + it * 128;
            const int m = i >> 6, k = i & 63;
            cp4(sA + (uint32_t)(m * AP + k) * 4,
                &X[(size_t)(m0 + m) * DIN + k0 + k]);
        }
        // B: 64 k x 64 n, 16B cp.async
        #pragma unroll
        for (int it = 0; it < 8; ++it) {
            const int i = tid + it * 128;
            const int k = i >> 4, c4 = (i & 15) << 2;
            cp16(sB + (uint32_t)(k * BP + c4) * 4,
                 &Wm[(size_t)(k0 + k) * U_ + c4]);
        }
        cp_commit();
    };

    stage_load(0, 0);

    for (int c = 0; c < 8; ++c) {
        cp_wait0();
        __syncthreads();
        if (c + 1 < 8) stage_load((c + 1) & 1, c + 1);

        const float* As = prsm + (c & 1) * STG_FL;
        const float* Bs = As + 8832;
        const float* a0 = As + (tym * 8 + 0) * AP;
        const float* a1 = As + (tym * 8 + 1) * AP;
        const float* a2 = As + (tym * 8 + 2) * AP;
        const float* a3 = As + (tym * 8 + 3) * AP;
        const float* a4 = As + (tym * 8 + 4) * AP;
        const float* a5 = As + (tym * 8 + 5) * AP;
        const float* a6 = As + (tym * 8 + 6) * AP;
        const float* a7 = As + (tym * 8 + 7) * AP;
        const float* bp = Bs + tx * 8;

        #pragma unroll 8
        for (int k = 0; k < 64; ++k) {
            ulonglong2 b01 = *(const ulonglong2*)&bp[k * BP];
            ulonglong2 b23 = *(const ulonglong2*)&bp[k * BP + 4];
            ull d0 = dup2(a0[k]); fma2(acc[0][0], d0, b01.x); fma2(acc[0][1], d0, b01.y);
                                  fma2(acc[0][2], d0, b23.x); fma2(acc[0][3], d0, b23.y);
            ull d1 = dup2(a1[k]); fma2(acc[1][0], d1, b01.x); fma2(acc[1][1], d1, b01.y);
                                  fma2(acc[1][2], d1, b23.x); fma2(acc[1][3], d1, b23.y);
            ull d2 = dup2(a2[k]); fma2(acc[2][0], d2, b01.x); fma2(acc[2][1], d2, b01.y);
                                  fma2(acc[2][2], d2, b23.x); fma2(acc[2][3], d2, b23.y);
            ull d3 = dup2(a3[k]); fma2(acc[3][0], d3, b01.x); fma2(acc[3][1], d3, b01.y);
                                  fma2(acc[3][2], d3, b23.x); fma2(acc[3][3], d3, b23.y);
            ull d4 = dup2(a4[k]); fma2(acc[4][0], d4, b01.x); fma2(acc[4][1], d4, b01.y);
                                  fma2(acc[4][2], d4, b23.x); fma2(acc[4][3], d4, b23.y);
            ull d5 = dup2(a5[k]); fma2(acc[5][0], d5, b01.x); fma2(acc[5][1], d5, b01.y);
                                  fma2(acc[5][2], d5, b23.x); fma2(acc[5][3], d5, b23.y);
            ull d6 = dup2(a6[k]); fma2(acc[6][0], d6, b01.x); fma2(acc[6][1], d6, b01.y);
                                  fma2(acc[6][2], d6, b23.x); fma2(acc[6][3], d6, b23.y);
            ull d7 = dup2(a7[k]); fma2(acc[7][0], d7, b01.x); fma2(acc[7][1], d7, b01.y);
                                  fma2(acc[7][2], d7, b23.x); fma2(acc[7][3], d7, b23.y);
        }
        __syncthreads();
    }

    // epilogue: bias + store
    float bias[8];
    #pragma unroll
    for (int cc = 0; cc < 8; ++cc) bias[cc] = bm[tx * 8 + cc];
    #pragma unroll
    for (int i = 0; i < 8; ++i) {
        float2 e0 = unpk(acc[i][0]);
        float2 e1 = unpk(acc[i][1]);
        float2 e2 = unpk(acc[i][2]);
        float2 e3 = unpk(acc[i][3]);
        float4 o0 = {e0.x + bias[0], e0.y + bias[1], e1.x + bias[2], e1.y + bias[3]};
        float4 o1 = {e2.x + bias[4], e2.y + bias[5], e3.x + bias[6], e3.y + bias[7]};
        const size_t row = (size_t)(m0 + tym * 8 + i) * U_;
        *(float4*)&O[row + tx * 8]     = o0;
        *(float4*)&O[row + tx * 8 + 4] = o1;
    }
}

// ======================= Kernel B: banded attention (R7, measured 41.4us) =======================
#define TJ   32
#define NBK  160
#define NBV  162
#define KP   68

__device__ __forceinline__ int off_of(int s)
{
    if (s <= 32)   return s * 33 + (s * (s - 1)) / 2;
    if (s <= 2016) return 1552 + (s - 32) * 65;
    return 130512 + ((2145 - s) * (s - 2016)) / 2;
}

extern __shared__ float sm_b[];

__global__ __launch_bounds__(512, 2)
void attn_kernel(float* __restrict__ out)
{
    float* Ks = sm_b;
    float* Vs = Ks + NBK * KP;
    float* Qs = Vs + NBV * 64;
    float* Es = Qs + TJ * 64;

    const int b     = blockIdx.y;
    const int j0    = blockIdx.x * TJ;
    const int tid   = threadIdx.x;
    const int ubase = j0 - 64;

    {
        const size_t gbase = (size_t)b * S_ * U_;
        for (int i = tid; i < TJ * 16; i += 512)
            *(float4*)&Qs[i * 4] = *(const float4*)&g_Q[gbase + (size_t)j0 * U_ + i * 4];
        for (int i = tid; i < NBK * 16; i += 512) {
            const int ug = i >> 4, d4 = (i & 15) << 2;
            int u = ubase + ug;
            u = (u < 0) ? 0 : ((u > S_ - 1) ? S_ - 1 : u);
            *(float4*)&Ks[ug * KP + d4] = *(const float4*)&g_K[gbase + (size_t)u * U_ + d4];
            *(float4*)&Vs[ug * 64 + d4] = *(const float4*)&g_V[gbase + (size_t)u * U_ + d4];
        }
        for (int i = tid; i < 2 * 16; i += 512) {
            const int ug = 160 + (i >> 4), d4 = (i & 15) << 2;
            *(float4*)&Vs[ug * 64 + d4] = make_float4(0.f, 0.f, 0.f, 0.f);
        }
        for (int i = tid; i < TJ * 132 / 4; i += 512)
            *(float4*)&Es[i * 4] = make_float4(0.f, 0.f, 0.f, 0.f);
    }
    __syncthreads();

    const int w    = tid >> 5;
    const int lane = tid & 31;
    const int jg   = lane >> 4;
    const int ul   = lane & 15;
    const int j_a  = j0 + 2 * w;
    const int jme  = j_a + jg;

    {
        float acc[9];
        int rowoff[9];
        #pragma unroll
        for (int t = 0; t < 9; ++t) {
            acc[t] = 0.f;
            int r = ul + 16 * t; if (r > 129) r = 129;
            rowoff[t] = (2 * w + r) * KP;
        }
        const float* qp = Qs + (2 * w + jg) * 64;
        #pragma unroll 4
        for (int d4 = 0; d4 < 64; d4 += 4) {
            float4 q = *(const float4*)&qp[d4];
            #pragma unroll
            for (int t = 0; t < 9; ++t) {
                float4 kf = *(const float4*)&Ks[rowoff[t] + d4];
                acc[t] += q.x * kf.x + q.y * kf.y + q.z * kf.z + q.w * kf.w;
            }
        }
        const float NEG_INF = __int_as_float(0xff800000);
        float sc[9], m = NEG_INF;
        #pragma unroll
        for (int t = 0; t < 9; ++t) {
            const int r  = ul + 16 * t;
            const int uu = r - jg;
            const int u  = ubase + 2 * w + r;
            const bool valid = (uu >= 0) && (uu <= 128) && (u >= 0) && (u < S_);
            sc[t] = valid ? acc[t] * 0.125f : NEG_INF;
            m = fmaxf(m, sc[t]);
        }
        #pragma unroll
        for (int off = 8; off > 0; off >>= 1)
            m = fmaxf(m, __shfl_xor_sync(0xffffffffu, m, off));
        float* erow = Es + (2 * w + jg) * 132;
        #pragma unroll
        for (int t = 0; t < 9; ++t) {
            const int uu = ul + 16 * t - jg;
            if (uu >= 0 && uu <= 128)
                erow[uu] = __expf(sc[t] - m);
        }
    }
    __syncthreads();

    {
        const int dl = lane & 15;
        const int smin_u = (j_a - 32 > 0) ? (j_a - 32) : 0;
        const int smax_u = (j_a + 33 < S_ - 1) ? (j_a + 33) : (S_ - 1);
        const int slo = (jme - 32 > 0) ? (jme - 32) : 0;
        const int shi = (jme + 32 < S_ - 1) ? (jme + 32) : (S_ - 1);

        const float* ej = Es + (2 * w + jg) * 132 + 64 - jme;
        float Dv = 0.f; ull n0 = 0ull, n1 = 0ull;
        {
            const int ulo = (smin_u - 32 > 0) ? (smin_u - 32) : 0;
            const int uhi = (smin_u + 33 < S_) ? (smin_u + 33) : S_;
            const float* pe = ej + ulo;
            const float* pv = Vs + (ulo - ubase) * 64 + dl * 4;
            for (int u = ulo; u < uhi; ++u) {
                const float e = *pe++;
                const ulonglong2 v = *(const ulonglong2*)pv; pv += 64;
                const ull ed = dup2(e);
                fma2(n0, ed, v.x); fma2(n1, ed, v.y);
                Dv += e;
            }
        }

        const int start0 = (smin_u - 32 > 0) ? (smin_u - 32) : 0;
        float* po = out + (size_t)b * L_OUT * U_
                        + ((size_t)off_of(smin_u) + (jme - start0)) * U_ + dl * 4;
        const float* pea = ej + smin_u + 33;
        const float* pes = ej + smin_u - 32;
        const float* pva = Vs + (smin_u + 33 - ubase) * 64 + dl * 4;
        const float* pvs = Vs + (smin_u - 32 - ubase) * 64 + dl * 4;

        for (int s = smin_u; s <= smax_u; ++s) {
            if (s >= slo && s <= shi) {
                const float invD = __fdividef(1.f, Dv);
                const ull dd = dup2(invD);
                ulonglong2 o; o.x = mul2(n0, dd); o.y = mul2(n1, dd);
                *(ulonglong2*)po = o;
            }
            int delta = s + 33; if (delta > 64) delta = 64;
            int d2 = 2079 - s;  if (d2 < delta) delta = d2;
            po += (size_t)delta * U_;

            const float ea = *pea++;
            const float es = *pes++;
            const ulonglong2 va = *(const ulonglong2*)pva; pva += 64;
            const ulonglong2 vv = *(const ulonglong2*)pvs; pvs += 64;
            const ull ead = dup2(ea);
            fma2(n0, ead, va.x); fma2(n1, ead, va.y);
            const ull esd = dup2(-es);
            fma2(n0, esd, vv.x); fma2(n1, esd, vv.y);
            Dv += (ea - es);
        }
    }
}

// ======================= launch =======================
extern "C" void kernel_launch(void* const* d_in, const int* in_sizes, int n_in,
                              void* d_out, int out_size)
{
    const float* query = (const float*)d_in[0];
    const float* value = (const float*)d_in[1];
    const float* Wq    = (const float*)d_in[2];
    const float* bq    = (const float*)d_in[3];
    const float* Wk    = (const float*)d_in[4];
    const float* bk    = (const float*)d_in[5];
    const float* Wv    = (const float*)d_in[6];
    const float* bv    = (const float*)d_in[7];
    float* out = (float*)d_out;

    cudaFuncSetAttribute(proj_kernel, cudaFuncAttributeMaxDynamicSharedMemorySize, PROJ_SMEM);
    dim3 gA(8192 / 128, 3);
    proj_kernel<<<gA, 128, PROJ_SMEM>>>(query, value, Wq, bq, Wk, bk, Wv, bv);

    const int smem_bytes = (NBK * KP + NBV * 64 + TJ * 64 + TJ * 132) * (int)sizeof(float);
    cudaFuncSetAttribute(attn_kernel, cudaFuncAttributeMaxDynamicSharedMemorySize, smem_bytes);
    dim3 gB(S_ / TJ, B_);
    attn_kernel<<<gB, 512, smem_bytes>>>(out);
}

// round 11
// speedup vs baseline: 1.2348x; 1.0233x over previous
#include <cuda_runtime.h>
#include <math.h>
#include <stdint.h>

#define B_   4
#define S_   2048
#define DIN  512
#define U_   64
#define L_OUT 132064

typedef unsigned long long ull;

// ---------------- f32x2 packed helpers (sm_103a) ----------------
__device__ __forceinline__ ull dup2(float x) {
    ull r; asm("mov.b64 %0, {%1, %1};" : "=l"(r) : "f"(x)); return r;
}
__device__ __forceinline__ void fma2(ull &d, ull a, ull b) {
    asm("fma.rn.f32x2 %0, %1, %2, %3;" : "=l"(d) : "l"(a), "l"(b), "l"(d));
}
__device__ __forceinline__ ull mul2(ull a, ull b) {
    ull d; asm("mul.rn.f32x2 %0, %1, %2;" : "=l"(d) : "l"(a), "l"(b)); return d;
}
__device__ __forceinline__ float2 unpk(ull v) {
    float2 f; asm("mov.b64 {%0, %1}, %2;" : "=f"(f.x), "=f"(f.y) : "l"(v)); return f;
}

// ---------------- cp.async helpers ----------------
__device__ __forceinline__ uint32_t smem_u32(const void* p) {
    uint32_t a;
    asm("{ .reg .u64 t; cvta.to.shared.u64 t, %1; cvt.u32.u64 %0, t; }" : "=r"(a) : "l"(p));
    return a;
}
__device__ __forceinline__ void cp16(uint32_t dst, const void* src) {
    asm volatile("cp.async.cg.shared.global [%0], [%1], 16;" :: "r"(dst), "l"(src));
}
__device__ __forceinline__ void cp_commit() {
    asm volatile("cp.async.commit_group;" ::: "memory");
}
__device__ __forceinline__ void cp_wait0() {
    asm volatile("cp.async.wait_group 0;" ::: "memory");
}

// ---------------- scratch ----------------
__device__ float g_Q[B_ * S_ * U_];
__device__ float g_K[B_ * S_ * U_];
__device__ float g_V[B_ * S_ * U_];

// ======================= Kernel A: QKV projections (f32x2, M64 tiles) =======================
// Tile M=64 x N=64, 128 threads, per-thread 4m x 8n (4 n-pairs). K chunks of 64.
// cp.async 16B double-buffer. A [64][68] row-major, B [64][68].
#define AP  68
#define BP  68
#define STG_FL (64 * AP + 64 * BP)   // 8704 floats per stage
#define PROJ_SMEM (2 * STG_FL * 4)   // 69632 B

extern __shared__ float prsm[];

__global__ __launch_bounds__(128, 3)
void proj_kernel(const float* __restrict__ query,
                 const float* __restrict__ value,
                 const float* __restrict__ Wq, const float* __restrict__ bq,
                 const float* __restrict__ Wk, const float* __restrict__ bk,
                 const float* __restrict__ Wv, const float* __restrict__ bv)
{
    const int p = blockIdx.y;
    const float* X  = (p == 0) ? query : value;
    const float* Wm = (p == 0) ? Wq : ((p == 1) ? Wk : Wv);
    const float* bm = (p == 0) ? bq : ((p == 1) ? bk : bv);
    float* O        = (p == 0) ? g_Q : ((p == 1) ? g_K : g_V);

    const int m0  = blockIdx.x * 64;
    const int tid = threadIdx.x;

    const uint32_t sbase = smem_u32(prsm);

    // compute roles
    const int tx  = tid & 7;         // n: cols tx*8 .. tx*8+7 (4 pairs)
    const int tym = tid >> 3;        // m: rows tym*4 .. tym*4+3 (0..15)

    ull acc[4][4];
    #pragma unroll
    for (int i = 0; i < 4; ++i)
        #pragma unroll
        for (int j = 0; j < 4; ++j) acc[i][j] = 0ull;

    // ---- stage loader: all 16B cp.async ----
    auto stage_load = [&](int buf, int c) {
        const int k0 = c * 64;
        const uint32_t sA = sbase + (uint32_t)(buf * STG_FL) * 4;
        const uint32_t sB = sA + (uint32_t)(64 * AP) * 4;
        // A: 64 rows x 16 float4
        #pragma unroll
        for (int it = 0; it < 8; ++it) {
            const int i = tid + it * 128;
            const int m = i >> 4, k4 = (i & 15) << 2;
            cp16(sA + (uint32_t)(m * AP + k4) * 4,
                 &X[(size_t)(m0 + m) * DIN + k0 + k4]);
        }
        // B: 64 k-rows x 16 float4
        #pragma unroll
        for (int it = 0; it < 8; ++it) {
            const int i = tid + it * 128;
            const int k = i >> 4, c4 = (i & 15) << 2;
            cp16(sB + (uint32_t)(k * BP + c4) * 4,
                 &Wm[(size_t)(k0 + k) * U_ + c4]);
        }
        cp_commit();
    };

    stage_load(0, 0);

    for (int c = 0; c < 8; ++c) {
        cp_wait0();
        __syncthreads();
        if (c + 1 < 8) stage_load((c + 1) & 1, c + 1);

        const float* As = prsm + (c & 1) * STG_FL;
        const float* Bs = As + 64 * AP;
        const float* arow = As + tym * 4 * AP;
        const float* bp   = Bs + tx * 8;

        #pragma unroll 4
        for (int k4 = 0; k4 < 64; k4 += 4) {
            float4 af0 = *(const float4*)&arow[0 * AP + k4];
            float4 af1 = *(const float4*)&arow[1 * AP + k4];
            float4 af2 = *(const float4*)&arow[2 * AP + k4];
            float4 af3 = *(const float4*)&arow[3 * AP + k4];
            #pragma unroll
            for (int kk = 0; kk < 4; ++kk) {
                ulonglong2 b01 = *(const ulonglong2*)&bp[(k4 + kk) * BP];
                ulonglong2 b23 = *(const ulonglong2*)&bp[(k4 + kk) * BP + 4];
                const float a0s = (kk == 0) ? af0.x : (kk == 1) ? af0.y : (kk == 2) ? af0.z : af0.w;
                const float a1s = (kk == 0) ? af1.x : (kk == 1) ? af1.y : (kk == 2) ? af1.z : af1.w;
                const float a2s = (kk == 0) ? af2.x : (kk == 1) ? af2.y : (kk == 2) ? af2.z : af2.w;
                const float a3s = (kk == 0) ? af3.x : (kk == 1) ? af3.y : (kk == 2) ? af3.z : af3.w;
                ull d0 = dup2(a0s), d1 = dup2(a1s), d2 = dup2(a2s), d3 = dup2(a3s);
                fma2(acc[0][0], d0, b01.x); fma2(acc[0][1], d0, b01.y);
                fma2(acc[0][2], d0, b23.x); fma2(acc[0][3], d0, b23.y);
                fma2(acc[1][0], d1, b01.x); fma2(acc[1][1], d1, b01.y);
                fma2(acc[1][2], d1, b23.x); fma2(acc[1][3], d1, b23.y);
                fma2(acc[2][0], d2, b01.x); fma2(acc[2][1], d2, b01.y);
                fma2(acc[2][2], d2, b23.x); fma2(acc[2][3], d2, b23.y);
                fma2(acc[3][0], d3, b01.x); fma2(acc[3][1], d3, b01.y);
                fma2(acc[3][2], d3, b23.x); fma2(acc[3][3], d3, b23.y);
            }
        }
        __syncthreads();
    }

    // epilogue: bias + store
    float bias[8];
    #pragma unroll
    for (int cc = 0; cc < 8; ++cc) bias[cc] = bm[tx * 8 + cc];
    #pragma unroll
    for (int i = 0; i < 4; ++i) {
        float2 e0 = unpk(acc[i][0]);
        float2 e1 = unpk(acc[i][1]);
        float2 e2 = unpk(acc[i][2]);
        float2 e3 = unpk(acc[i][3]);
        float4 o0 = {e0.x + bias[0], e0.y + bias[1], e1.x + bias[2], e1.y + bias[3]};
        float4 o1 = {e2.x + bias[4], e2.y + bias[5], e3.x + bias[6], e3.y + bias[7]};
        const size_t row = (size_t)(m0 + tym * 4 + i) * U_;
        *(float4*)&O[row + tx * 8]     = o0;
        *(float4*)&O[row + tx * 8 + 4] = o1;
    }
}

// ======================= Kernel B: banded attention (R7, measured 41.4us) =======================
#define TJ   32
#define NBK  160
#define NBV  162
#define KP   68

__device__ __forceinline__ int off_of(int s)
{
    if (s <= 32)   return s * 33 + (s * (s - 1)) / 2;
    if (s <= 2016) return 1552 + (s - 32) * 65;
    return 130512 + ((2145 - s) * (s - 2016)) / 2;
}

extern __shared__ float sm_b[];

__global__ __launch_bounds__(512, 2)
void attn_kernel(float* __restrict__ out)
{
    float* Ks = sm_b;
    float* Vs = Ks + NBK * KP;
    float* Qs = Vs + NBV * 64;
    float* Es = Qs + TJ * 64;

    const int b     = blockIdx.y;
    const int j0    = blockIdx.x * TJ;
    const int tid   = threadIdx.x;
    const int ubase = j0 - 64;

    {
        const size_t gbase = (size_t)b * S_ * U_;
        for (int i = tid; i < TJ * 16; i += 512)
            *(float4*)&Qs[i * 4] = *(const float4*)&g_Q[gbase + (size_t)j0 * U_ + i * 4];
        for (int i = tid; i < NBK * 16; i += 512) {
            const int ug = i >> 4, d4 = (i & 15) << 2;
            int u = ubase + ug;
            u = (u < 0) ? 0 : ((u > S_ - 1) ? S_ - 1 : u);
            *(float4*)&Ks[ug * KP + d4] = *(const float4*)&g_K[gbase + (size_t)u * U_ + d4];
            *(float4*)&Vs[ug * 64 + d4] = *(const float4*)&g_V[gbase + (size_t)u * U_ + d4];
        }
        for (int i = tid; i < 2 * 16; i += 512) {
            const int ug = 160 + (i >> 4), d4 = (i & 15) << 2;
            *(float4*)&Vs[ug * 64 + d4] = make_float4(0.f, 0.f, 0.f, 0.f);
        }
        for (int i = tid; i < TJ * 132 / 4; i += 512)
            *(float4*)&Es[i * 4] = make_float4(0.f, 0.f, 0.f, 0.f);
    }
    __syncthreads();

    const int w    = tid >> 5;
    const int lane = tid & 31;
    const int jg   = lane >> 4;
    const int ul   = lane & 15;
    const int j_a  = j0 + 2 * w;
    const int jme  = j_a + jg;

    {
        float acc[9];
        int rowoff[9];
        #pragma unroll
        for (int t = 0; t < 9; ++t) {
            acc[t] = 0.f;
            int r = ul + 16 * t; if (r > 129) r = 129;
            rowoff[t] = (2 * w + r) * KP;
        }
        const float* qp = Qs + (2 * w + jg) * 64;
        #pragma unroll 4
        for (int d4 = 0; d4 < 64; d4 += 4) {
            float4 q = *(const float4*)&qp[d4];
            #pragma unroll
            for (int t = 0; t < 9; ++t) {
                float4 kf = *(const float4*)&Ks[rowoff[t] + d4];
                acc[t] += q.x * kf.x + q.y * kf.y + q.z * kf.z + q.w * kf.w;
            }
        }
        const float NEG_INF = __int_as_float(0xff800000);
        float sc[9], m = NEG_INF;
        #pragma unroll
        for (int t = 0; t < 9; ++t) {
            const int r  = ul + 16 * t;
            const int uu = r - jg;
            const int u  = ubase + 2 * w + r;
            const bool valid = (uu >= 0) && (uu <= 128) && (u >= 0) && (u < S_);
            sc[t] = valid ? acc[t] * 0.125f : NEG_INF;
            m = fmaxf(m, sc[t]);
        }
        #pragma unroll
        for (int off = 8; off > 0; off >>= 1)
            m = fmaxf(m, __shfl_xor_sync(0xffffffffu, m, off));
        float* erow = Es + (2 * w + jg) * 132;
        #pragma unroll
        for (int t = 0; t < 9; ++t) {
            const int uu = ul + 16 * t - jg;
            if (uu >= 0 && uu <= 128)
                erow[uu] = __expf(sc[t] - m);
        }
    }
    __syncthreads();

    {
        const int dl = lane & 15;
        const int smin_u = (j_a - 32 > 0) ? (j_a - 32) : 0;
        const int smax_u = (j_a + 33 < S_ - 1) ? (j_a + 33) : (S_ - 1);
        const int slo = (jme - 32 > 0) ? (jme - 32) : 0;
        const int shi = (jme + 32 < S_ - 1) ? (jme + 32) : (S_ - 1);

        const float* ej = Es + (2 * w + jg) * 132 + 64 - jme;
        float Dv = 0.f; ull n0 = 0ull, n1 = 0ull;
        {
            const int ulo = (smin_u - 32 > 0) ? (smin_u - 32) : 0;
            const int uhi = (smin_u + 33 < S_) ? (smin_u + 33) : S_;
            const float* pe = ej + ulo;
            const float* pv = Vs + (ulo - ubase) * 64 + dl * 4;
            for (int u = ulo; u < uhi; ++u) {
                const float e = *pe++;
                const ulonglong2 v = *(const ulonglong2*)pv; pv += 64;
                const ull ed = dup2(e);
                fma2(n0, ed, v.x); fma2(n1, ed, v.y);
                Dv += e;
            }
        }

        const int start0 = (smin_u - 32 > 0) ? (smin_u - 32) : 0;
        float* po = out + (size_t)b * L_OUT * U_
                        + ((size_t)off_of(smin_u) + (jme - start0)) * U_ + dl * 4;
        const float* pea = ej + smin_u + 33;
        const float* pes = ej + smin_u - 32;
        const float* pva = Vs + (smin_u + 33 - ubase) * 64 + dl * 4;
        const float* pvs = Vs + (smin_u - 32 - ubase) * 64 + dl * 4;

        for (int s = smin_u; s <= smax_u; ++s) {
            if (s >= slo && s <= shi) {
                const float invD = __fdividef(1.f, Dv);
                const ull dd = dup2(invD);
                ulonglong2 o; o.x = mul2(n0, dd); o.y = mul2(n1, dd);
                *(ulonglong2*)po = o;
            }
            int delta = s + 33; if (delta > 64) delta = 64;
            int d2 = 2079 - s;  if (d2 < delta) delta = d2;
            po += (size_t)delta * U_;

            const float ea = *pea++;
            const float es = *pes++;
            const ulonglong2 va = *(const ulonglong2*)pva; pva += 64;
            const ulonglong2 vv = *(const ulonglong2*)pvs; pvs += 64;
            const ull ead = dup2(ea);
            fma2(n0, ead, va.x); fma2(n1, ead, va.y);
            const ull esd = dup2(-es);
            fma2(n0, esd, vv.x); fma2(n1, esd, vv.y);
            Dv += (ea - es);
        }
    }
}

// ======================= launch =======================
extern "C" void kernel_launch(void* const* d_in, const int* in_sizes, int n_in,
                              void* d_out, int out_size)
{
    const float* query = (const float*)d_in[0];
    const float* value = (const float*)d_in[1];
    const float* Wq    = (const float*)d_in[2];
    const float* bq    = (const float*)d_in[3];
    const float* Wk    = (const float*)d_in[4];
    const float* bk    = (const float*)d_in[5];
    const float* Wv    = (const float*)d_in[6];
    const float* bv    = (const float*)d_in[7];
    float* out = (float*)d_out;

    cudaFuncSetAttribute(proj_kernel, cudaFuncAttributeMaxDynamicSharedMemorySize, PROJ_SMEM);
    dim3 gA(8192 / 64, 3);
    proj_kernel<<<gA, 128, PROJ_SMEM>>>(query, value, Wq, bq, Wk, bk, Wv, bv);

    const int smem_bytes = (NBK * KP + NBV * 64 + TJ * 64 + TJ * 132) * (int)sizeof(float);
    cudaFuncSetAttribute(attn_kernel, cudaFuncAttributeMaxDynamicSharedMemorySize, smem_bytes);
    dim3 gB(S_ / TJ, B_);
    attn_kernel<<<gB, 512, smem_bytes>>>(out);
}

// round 14
// speedup vs baseline: 1.5362x; 1.2441x over previous
#include <cuda_runtime.h>
#include <math.h>
#include <stdint.h>

#define B_   4
#define S_   2048
#define DIN  512
#define U_   64
#define L_OUT 132064

typedef unsigned long long ull;

// ---------------- f32x2 packed helpers (sm_103a) ----------------
__device__ __forceinline__ ull dup2(float x) {
    ull r; asm("mov.b64 %0, {%1, %1};" : "=l"(r) : "f"(x)); return r;
}
__device__ __forceinline__ void fma2(ull &d, ull a, ull b) {
    asm("fma.rn.f32x2 %0, %1, %2, %3;" : "=l"(d) : "l"(a), "l"(b), "l"(d));
}
__device__ __forceinline__ ull mul2(ull a, ull b) {
    ull d; asm("mul.rn.f32x2 %0, %1, %2;" : "=l"(d) : "l"(a), "l"(b)); return d;
}
__device__ __forceinline__ float2 unpk(ull v) {
    float2 f; asm("mov.b64 {%0, %1}, %2;" : "=f"(f.x), "=f"(f.y) : "l"(v)); return f;
}

// ---------------- cp.async helpers ----------------
__device__ __forceinline__ uint32_t smem_u32(const void* p) {
    uint32_t a;
    asm("{ .reg .u64 t; cvta.to.shared.u64 t, %1; cvt.u32.u64 %0, t; }" : "=r"(a) : "l"(p));
    return a;
}
__device__ __forceinline__ void cp16(uint32_t dst, const void* src) {
    asm volatile("cp.async.cg.shared.global [%0], [%1], 16;" :: "r"(dst), "l"(src));
}
__device__ __forceinline__ void cp_commit() {
    asm volatile("cp.async.commit_group;" ::: "memory");
}
__device__ __forceinline__ void cp_wait0() {
    asm volatile("cp.async.wait_group 0;" ::: "memory");
}

// ---------------- scratch ----------------
__device__ float g_Q[B_ * S_ * U_];
__device__ float g_K[B_ * S_ * U_];
__device__ float g_V[B_ * S_ * U_];

// ======================= Kernel A: QKV projections =======================
// Tile M=64, 128 threads (4 warps). Warp w owns m rows 16w..16w+15.
// Lane l owns output n-pair (2l, 2l+1): B operand = LDS.64 from k-major W tile
// (conflict-free), A operand = broadcast LDS.128 + dup2.
#define AP  64
#define BP  64
#define STG_FL (64 * AP + 64 * BP)   // 8192 floats = 32KB per stage
#define PROJ_SMEM (2 * STG_FL * 4)   // 64KB

extern __shared__ float prsm[];

__global__ __launch_bounds__(128, 3)
void proj_kernel(const float* __restrict__ query,
                 const float* __restrict__ value,
                 const float* __restrict__ Wq, const float* __restrict__ bq,
                 const float* __restrict__ Wk, const float* __restrict__ bk,
                 const float* __restrict__ Wv, const float* __restrict__ bv)
{
    const int p = blockIdx.y;
    const float* X  = (p == 0) ? query : value;
    const float* Wm = (p == 0) ? Wq : ((p == 1) ? Wk : Wv);
    const float* bm = (p == 0) ? bq : ((p == 1) ? bk : bv);
    float* O        = (p == 0) ? g_Q : ((p == 1) ? g_K : g_V);

    const int m0   = blockIdx.x * 64;
    const int tid  = threadIdx.x;
    const int w    = tid >> 5;
    const int lane = tid & 31;

    const uint32_t sbase = smem_u32(prsm);

    ull acc[16];
    #pragma unroll
    for (int i = 0; i < 16; ++i) acc[i] = 0ull;

    // ---- stage loader: all 16B cp.async, fully coalesced ----
    auto stage_load = [&](int buf, int c) {
        const int k0 = c * 64;
        const uint32_t sA = sbase + (uint32_t)(buf * STG_FL) * 4;
        const uint32_t sB = sA + (uint32_t)(64 * AP) * 4;
        #pragma unroll
        for (int it = 0; it < 8; ++it) {
            const int i = tid + it * 128;
            const int m = i >> 4, k4 = (i & 15) << 2;
            cp16(sA + (uint32_t)(m * AP + k4) * 4,
                 &X[(size_t)(m0 + m) * DIN + k0 + k4]);
        }
        #pragma unroll
        for (int it = 0; it < 8; ++it) {
            const int i = tid + it * 128;
            const int k = i >> 4, c4 = (i & 15) << 2;
            cp16(sB + (uint32_t)(k * BP + c4) * 4,
                 &Wm[(size_t)(k0 + k) * U_ + c4]);
        }
        cp_commit();
    };

    stage_load(0, 0);

    for (int c = 0; c < 8; ++c) {
        cp_wait0();
        __syncthreads();
        if (c + 1 < 8) stage_load((c + 1) & 1, c + 1);

        const float* As = prsm + (c & 1) * STG_FL;
        const float* Bs = As + 64 * AP;
        const float* arow = As + (w * 16) * AP;     // my warp's 16 m-rows
        const float* bp   = Bs + 2 * lane;          // my n-pair column

        #pragma unroll 4
        for (int k4 = 0; k4 < 64; k4 += 4) {
            // B pairs for 4 consecutive k (LDS.64, conflict-free)
            ull b0 = *(const ull*)&bp[(k4 + 0) * BP];
            ull b1 = *(const ull*)&bp[(k4 + 1) * BP];
            ull b2 = *(const ull*)&bp[(k4 + 2) * BP];
            ull b3 = *(const ull*)&bp[(k4 + 3) * BP];
            #pragma unroll
            for (int mg = 0; mg < 16; mg += 4) {
                float4 a0 = *(const float4*)&arow[(mg + 0) * AP + k4];
                float4 a1 = *(const float4*)&arow[(mg + 1) * AP + k4];
                float4 a2 = *(const float4*)&arow[(mg + 2) * AP + k4];
                float4 a3 = *(const float4*)&arow[(mg + 3) * AP + k4];
                fma2(acc[mg + 0], dup2(a0.x), b0); fma2(acc[mg + 0], dup2(a0.y), b1);
                fma2(acc[mg + 0], dup2(a0.z), b2); fma2(acc[mg + 0], dup2(a0.w), b3);
                fma2(acc[mg + 1], dup2(a1.x), b0); fma2(acc[mg + 1], dup2(a1.y), b1);
                fma2(acc[mg + 1], dup2(a1.z), b2); fma2(acc[mg + 1], dup2(a1.w), b3);
                fma2(acc[mg + 2], dup2(a2.x), b0); fma2(acc[mg + 2], dup2(a2.y), b1);
                fma2(acc[mg + 2], dup2(a2.z), b2); fma2(acc[mg + 2], dup2(a2.w), b3);
                fma2(acc[mg + 3], dup2(a3.x), b0); fma2(acc[mg + 3], dup2(a3.y), b1);
                fma2(acc[mg + 3], dup2(a3.z), b2); fma2(acc[mg + 3], dup2(a3.w), b3);
            }
        }
        __syncthreads();
    }

    // epilogue: bias + store (lane's n-pair is contiguous: STG.64 per m)
    const float2 bb = *(const float2*)&bm[2 * lane];
    #pragma unroll
    for (int i = 0; i < 16; ++i) {
        float2 e = unpk(acc[i]);
        float2 o = {e.x + bb.x, e.y + bb.y};
        *(float2*)&O[(size_t)(m0 + w * 16 + i) * U_ + 2 * lane] = o;
    }
}

// ======================= Kernel B: banded attention (R7, measured ~41us) =======================
#define TJ   32
#define NBK  160
#define NBV  162
#define KP   68

__device__ __forceinline__ int off_of(int s)
{
    if (s <= 32)   return s * 33 + (s * (s - 1)) / 2;
    if (s <= 2016) return 1552 + (s - 32) * 65;
    return 130512 + ((2145 - s) * (s - 2016)) / 2;
}

extern __shared__ float sm_b[];

__global__ __launch_bounds__(512, 2)
void attn_kernel(float* __restrict__ out)
{
    float* Ks = sm_b;
    float* Vs = Ks + NBK * KP;
    float* Qs = Vs + NBV * 64;
    float* Es = Qs + TJ * 64;

    const int b     = blockIdx.y;
    const int j0    = blockIdx.x * TJ;
    const int tid   = threadIdx.x;
    const int ubase = j0 - 64;

    {
        const size_t gbase = (size_t)b * S_ * U_;
        for (int i = tid; i < TJ * 16; i += 512)
            *(float4*)&Qs[i * 4] = *(const float4*)&g_Q[gbase + (size_t)j0 * U_ + i * 4];
        for (int i = tid; i < NBK * 16; i += 512) {
            const int ug = i >> 4, d4 = (i & 15) << 2;
            int u = ubase + ug;
            u = (u < 0) ? 0 : ((u > S_ - 1) ? S_ - 1 : u);
            *(float4*)&Ks[ug * KP + d4] = *(const float4*)&g_K[gbase + (size_t)u * U_ + d4];
            *(float4*)&Vs[ug * 64 + d4] = *(const float4*)&g_V[gbase + (size_t)u * U_ + d4];
        }
        for (int i = tid; i < 2 * 16; i += 512) {
            const int ug = 160 + (i >> 4), d4 = (i & 15) << 2;
            *(float4*)&Vs[ug * 64 + d4] = make_float4(0.f, 0.f, 0.f, 0.f);
        }
        for (int i = tid; i < TJ * 132 / 4; i += 512)
            *(float4*)&Es[i * 4] = make_float4(0.f, 0.f, 0.f, 0.f);
    }
    __syncthreads();

    const int w    = tid >> 5;
    const int lane = tid & 31;
    const int jg   = lane >> 4;
    const int ul   = lane & 15;
    const int j_a  = j0 + 2 * w;
    const int jme  = j_a + jg;

    {
        float acc[9];
        int rowoff[9];
        #pragma unroll
        for (int t = 0; t < 9; ++t) {
            acc[t] = 0.f;
            int r = ul + 16 * t; if (r > 129) r = 129;
            rowoff[t] = (2 * w + r) * KP;
        }
        const float* qp = Qs + (2 * w + jg) * 64;
        #pragma unroll 4
        for (int d4 = 0; d4 < 64; d4 += 4) {
            float4 q = *(const float4*)&qp[d4];
            #pragma unroll
            for (int t = 0; t < 9; ++t) {
                float4 kf = *(const float4*)&Ks[rowoff[t] + d4];
                acc[t] += q.x * kf.x + q.y * kf.y + q.z * kf.z + q.w * kf.w;
            }
        }
        const float NEG_INF = __int_as_float(0xff800000);
        float sc[9], m = NEG_INF;
        #pragma unroll
        for (int t = 0; t < 9; ++t) {
            const int r  = ul + 16 * t;
            const int uu = r - jg;
            const int u  = ubase + 2 * w + r;
            const bool valid = (uu >= 0) && (uu <= 128) && (u >= 0) && (u < S_);
            sc[t] = valid ? acc[t] * 0.125f : NEG_INF;
            m = fmaxf(m, sc[t]);
        }
        #pragma unroll
        for (int off = 8; off > 0; off >>= 1)
            m = fmaxf(m, __shfl_xor_sync(0xffffffffu, m, off));
        float* erow = Es + (2 * w + jg) * 132;
        #pragma unroll
        for (int t = 0; t < 9; ++t) {
            const int uu = ul + 16 * t - jg;
            if (uu >= 0 && uu <= 128)
                erow[uu] = __expf(sc[t] - m);
        }
    }
    __syncthreads();

    {
        const int dl = lane & 15;
        const int smin_u = (j_a - 32 > 0) ? (j_a - 32) : 0;
        const int smax_u = (j_a + 33 < S_ - 1) ? (j_a + 33) : (S_ - 1);
        const int slo = (jme - 32 > 0) ? (jme - 32) : 0;
        const int shi = (jme + 32 < S_ - 1) ? (jme + 32) : (S_ - 1);

        const float* ej = Es + (2 * w + jg) * 132 + 64 - jme;
        float Dv = 0.f; ull n0 = 0ull, n1 = 0ull;
        {
            const int ulo = (smin_u - 32 > 0) ? (smin_u - 32) : 0;
            const int uhi = (smin_u + 33 < S_) ? (smin_u + 33) : S_;
            const float* pe = ej + ulo;
            const float* pv = Vs + (ulo - ubase) * 64 + dl * 4;
            for (int u = ulo; u < uhi; ++u) {
                const float e = *pe++;
                const ulonglong2 v = *(const ulonglong2*)pv; pv += 64;
                const ull ed = dup2(e);
                fma2(n0, ed, v.x); fma2(n1, ed, v.y);
                Dv += e;
            }
        }

        const int start0 = (smin_u - 32 > 0) ? (smin_u - 32) : 0;
        float* po = out + (size_t)b * L_OUT * U_
                        + ((size_t)off_of(smin_u) + (jme - start0)) * U_ + dl * 4;
        const float* pea = ej + smin_u + 33;
        const float* pes = ej + smin_u - 32;
        const float* pva = Vs + (smin_u + 33 - ubase) * 64 + dl * 4;
        const float* pvs = Vs + (smin_u - 32 - ubase) * 64 + dl * 4;

        for (int s = smin_u; s <= smax_u; ++s) {
            if (s >= slo && s <= shi) {
                const float invD = __fdividef(1.f, Dv);
                const ull dd = dup2(invD);
                ulonglong2 o; o.x = mul2(n0, dd); o.y = mul2(n1, dd);
                *(ulonglong2*)po = o;
            }
            int delta = s + 33; if (delta > 64) delta = 64;
            int d2 = 2079 - s;  if (d2 < delta) delta = d2;
            po += (size_t)delta * U_;

            const float ea = *pea++;
            const float es = *pes++;
            const ulonglong2 va = *(const ulonglong2*)pva; pva += 64;
            const ulonglong2 vv = *(const ulonglong2*)pvs; pvs += 64;
            const ull ead = dup2(ea);
            fma2(n0, ead, va.x); fma2(n1, ead, va.y);
            const ull esd = dup2(-es);
            fma2(n0, esd, vv.x); fma2(n1, esd, vv.y);
            Dv += (ea - es);
        }
    }
}

// ======================= launch =======================
extern "C" void kernel_launch(void* const* d_in, const int* in_sizes, int n_in,
                              void* d_out, int out_size)
{
    const float* query = (const float*)d_in[0];
    const float* value = (const float*)d_in[1];
    const float* Wq    = (const float*)d_in[2];
    const float* bq    = (const float*)d_in[3];
    const float* Wk    = (const float*)d_in[4];
    const float* bk    = (const float*)d_in[5];
    const float* Wv    = (const float*)d_in[6];
    const float* bv    = (const float*)d_in[7];
    float* out = (float*)d_out;

    cudaFuncSetAttribute(proj_kernel, cudaFuncAttributeMaxDynamicSharedMemorySize, PROJ_SMEM);
    dim3 gA(8192 / 64, 3);
    proj_kernel<<<gA, 128, PROJ_SMEM>>>(query, value, Wq, bq, Wk, bk, Wv, bv);

    const int smem_bytes = (NBK * KP + NBV * 64 + TJ * 64 + TJ * 132) * (int)sizeof(float);
    cudaFuncSetAttribute(attn_kernel, cudaFuncAttributeMaxDynamicSharedMemorySize, smem_bytes);
    dim3 gB(S_ / TJ, B_);
    attn_kernel<<<gB, 512, smem_bytes>>>(out);
}